// round 15
// baseline (speedup 1.0000x reference)
#include <cuda_runtime.h>
#include <cuda_fp16.h>
#include <math.h>
#include <stdint.h>

#define BATCH  32
#define SEQ    2048
#define DMODEL 256
#define HID    512
#define HID2   1024
#define INNER  1024
#define NTOK   (BATCH*SEQ)   // 65536
#define NC     32
#define CLEN   (SEQ/NC)      // 64
#define CONV_CHUNK 32
#define HBATCH (BATCH/2)
#define HROWS  (NTOK/2)      // 32768

// ---------------------------------------------------------------------------
// Scratch
// ---------------------------------------------------------------------------
__device__ float g_hs   [(size_t)NTOK*DMODEL];
__device__ float g_cA   [BATCH*NC*HID];
__device__ float g_cB   [BATCH*NC*HID];
__device__ float g_splam[HID];
__device__ float g_bil  [HID2];
__device__ __align__(256) __half2 g_ab[(size_t)NTOK*HID];
__device__ __align__(256) __half g_xzh[(size_t)NTOK*HID2];  // [xh | z]
__device__ __align__(256) __half g_xr [(size_t)NTOK*DMODEL];
__device__ __align__(256) __half g_xc [(size_t)NTOK*HID];
__device__ __align__(256) __half g_y  [(size_t)NTOK*HID];
__device__ __align__(256) __half g_hsh[(size_t)NTOK*DMODEL];
__device__ __align__(256) __half g_ff1[(size_t)NTOK*INNER];
__device__ __align__(256) __half g_wiT[HID2*DMODEL];
__device__ __align__(256) __half g_wgT[HID2*HID];
__device__ __align__(256) __half g_woT[DMODEL*HID];
__device__ __align__(256) __half g_f1T[INNER*DMODEL];
__device__ __align__(256) __half g_f2T[DMODEL*INNER];

// ---------------------------------------------------------------------------
// helpers
// ---------------------------------------------------------------------------
__device__ __forceinline__ uint32_t smem_u32(const void* p){
    uint32_t a;
    asm("{ .reg .u64 t; cvta.to.shared.u64 t, %1; cvt.u32.u64 %0, t; }"
        : "=r"(a) : "l"(p));
    return a;
}
__device__ __forceinline__ void cp_async16(uint32_t dst, const void* src){
    asm volatile("cp.async.cg.shared.global [%0], [%1], 16;" :: "r"(dst), "l"(src));
}
__device__ __forceinline__ void cp_commit(){ asm volatile("cp.async.commit_group;"); }

#define LDSM4(R, A) \
    asm volatile("ldmatrix.sync.aligned.m8n8.x4.shared.b16 {%0,%1,%2,%3}, [%4];" \
        : "=r"((R)[0]),"=r"((R)[1]),"=r"((R)[2]),"=r"((R)[3]) : "r"(A))

#define MMA_F16(C, A, B0, B1) \
    asm volatile("mma.sync.aligned.m16n8k16.row.col.f32.f16.f16.f32 " \
        "{%0,%1,%2,%3},{%4,%5,%6,%7},{%8,%9},{%0,%1,%2,%3};" \
        : "+f"((C)[0]),"+f"((C)[1]),"+f"((C)[2]),"+f"((C)[3]) \
        : "r"((A)[0]),"r"((A)[1]),"r"((A)[2]),"r"((A)[3]),"r"(B0),"r"(B1))

// ---------------------------------------------------------------------------
// fp16 GEMM (128x128 tile, 256 thr, BK=64, PROW=144), 3-stage cp.async
// pipeline with a single __syncthreads per K-chunk.
// mode: 0 = plain, 1 = silu, 2 = fused gates epilogue (+2 chunk scanA's)
// ---------------------------------------------------------------------------
#define BK    64
#define PROW  144                  // 128 data bytes + 16 pad
#define SZ_T  (128*PROW)           // 18432
#define OFF_B SZ_T
#define STAGE (2*SZ_T)             // 36864
#define GEMM_SMEM (3*STAGE)        // 110592 (2 CTAs/SM); >= overlay 34816

__global__ __launch_bounds__(256)
void mma_gemm(const __half* __restrict__ A, const __half* __restrict__ Bt,
              int M, int N, int K, int col0, int row0,
              const float* __restrict__ bias, int mode,
              float* __restrict__ Cf, __half* __restrict__ Ch)
{
    extern __shared__ __align__(128) char smem[];
    const uint32_t sb = smem_u32(smem);
    const int tid = threadIdx.x;
    const int wid = tid >> 5, lane = tid & 31;
    const long brow = (long)blockIdx.y * 128;
    const long bcol = (long)col0 + (long)blockIdx.x * 128;

    const int rowBase = (wid >> 2) * 64;
    const int colBase = (wid & 3) * 32;

    float acc[4][4][4];
#pragma unroll
    for (int a = 0; a < 4; a++)
#pragma unroll
        for (int b = 0; b < 4; b++)
#pragma unroll
            for (int c = 0; c < 4; c++) acc[a][b][c] = 0.f;

    const int nch = K / BK;

    auto load_stage = [&](int s, int cidx){
        const uint32_t base = sb + s * STAGE;
        const long kc = (long)cidx * BK;
#pragma unroll
        for (int i = tid; i < 1024; i += 256) {
            const int row = i >> 3, ch = i & 7;
            const uint32_t d = row * PROW + ch * 16;
            cp_async16(base + d,         A  + (brow + row) * (long)K + kc + ch * 8);
            cp_async16(base + OFF_B + d, Bt + (bcol + row) * (long)K + kc + ch * 8);
        }
        cp_commit();
    };

    // prologue: stages 0 and 1 in flight
    load_stage(0, 0);
    if (nch > 1) load_stage(1, 1);

    const int g = lane >> 3, r = lane & 7;

    int sidx = 0;                        // stage of chunk c
    for (int c = 0; c < nch; c++) {
        if (c + 1 < nch) asm volatile("cp.async.wait_group 1;" ::: "memory");
        else             asm volatile("cp.async.wait_group 0;" ::: "memory");
        __syncthreads();                 // data for chunk c visible; stage (c+2)%3 free
        if (c + 2 < nch) {
            int s2 = sidx + 2; if (s2 >= 3) s2 -= 3;
            load_stage(s2, c + 2);
        }

        const uint32_t st = sb + sidx * STAGE;
#pragma unroll
        for (int ks = 0; ks < 4; ks++) {
            const int k0 = ks * 16;
            uint32_t bf[2][4];
#pragma unroll
            for (int p = 0; p < 2; p++) {
                const uint32_t boff =
                    (uint32_t)(colBase + p*16 + ((g >> 1) << 3) + r) * PROW
                    + (uint32_t)(k0 + ((g & 1) << 3)) * 2;
                LDSM4(bf[p], st + OFF_B + boff);
            }
#pragma unroll
            for (int mi = 0; mi < 4; mi++) {
                const uint32_t aoff =
                    (uint32_t)(rowBase + mi*16 + r + ((g & 1) << 3)) * PROW
                    + (uint32_t)(k0 + ((g >> 1) << 3)) * 2;
                uint32_t af[4];
                LDSM4(af, st + aoff);
#pragma unroll
                for (int ni = 0; ni < 4; ni++) {
                    const int p = ni >> 1, q = (ni & 1) * 2;
                    MMA_F16(acc[mi][ni], af, bf[p][q], bf[p][q+1]);
                }
            }
        }
        if (++sidx == 3) sidx = 0;
    }

    const int gID = lane >> 2, tig = lane & 3;

    if (mode == 2) {
        __syncthreads();                 // all warps done reading pipeline smem
        // fused gates epilogue; tile rows = 2 scan chunks of CLEN=64
        __half2* sAB  = (__half2*)smem;
        float*   segb = (float*)(smem + 128*64*4);
#pragma unroll
        for (int mi = 0; mi < 4; mi++) {
#pragma unroll
            for (int ni = 0; ni < 4; ni++) {
                const long col = bcol + colBase + ni*8 + tig*2;
                const int hloc = (colBase >> 1) + ni*4 + tig;
                const int h    = (int)(col >> 1);
#pragma unroll
                for (int half = 0; half < 2; half++) {
                    const int  rloc = rowBase + mi*16 + gID + half*8;
                    const long arow = (long)row0 + brow + rloc;
                    const float rec = acc[mi][ni][half*2]   + g_bil[col];
                    const float inp = acc[mi][ni][half*2+1] + g_bil[col + 1];
                    const float sp = g_splam[h];
                    const float sr = __fdividef(1.f, 1.f + __expf(-rec));
                    const float om = -expm1f(-sp * sr);          // 1 - alpha
                    const float a  = 1.f - om;
                    const float si = __fdividef(1.f, 1.f + __expf(-inp));
                    const float xc = __half2float(g_xc[arow * HID + h]);
                    const float bp = sqrtf(1.f - a*a + 1e-8f) * si * xc;
                    const __half2 pk = __floats2half2_rn(om, bp);
                    g_ab[arow * HID + h] = pk;
                    sAB[rloc * 64 + hloc] = pk;
                }
            }
        }
        __syncthreads();
        const int ch  = tid & 63;
        const int seg = tid >> 6;
        const long abrow = (long)row0 + brow;
        const int b   = (int)(abrow >> 11);
        const int cc0 = (int)((abrow >> 6) & (NC - 1));
#pragma unroll
        for (int sub = 0; sub < 2; sub++) {
            float Aprod = 1.f, Bacc = 0.f;
            int rr = sub * 64 + seg * 16;
#pragma unroll 8
            for (int t = 0; t < 16; t++, rr++) {
                const __half2 pk = sAB[rr * 64 + ch];
                const float a = 1.f - __low2float(pk);
                const float p = __high2float(pk);
                Bacc = fmaf(a, Bacc, p);
                Aprod *= a;
            }
            segb[(ch * 4 + seg) * 2]     = Aprod;
            segb[(ch * 4 + seg) * 2 + 1] = Bacc;
            __syncthreads();
            if (tid < 64) {
                float At = 1.f, Bv = 0.f;
#pragma unroll
                for (int s2 = 0; s2 < 4; s2++) {
                    const float a = segb[(tid * 4 + s2) * 2];
                    const float p = segb[(tid * 4 + s2) * 2 + 1];
                    Bv = fmaf(a, Bv, p);
                    At *= a;
                }
                const int h = (int)(bcol >> 1) + tid;
                g_cA[(b*NC + cc0 + sub)*HID + h] = At;
                g_cB[(b*NC + cc0 + sub)*HID + h] = Bv;
            }
            __syncthreads();
        }
        return;
    }

#pragma unroll
    for (int mi = 0; mi < 4; mi++) {
#pragma unroll
        for (int ni = 0; ni < 4; ni++) {
            const long col = bcol + colBase + ni*8 + tig*2;
            float b0 = 0.f, b1 = 0.f;
            if (bias) { b0 = __ldg(&bias[col]); b1 = __ldg(&bias[col+1]); }
#pragma unroll
            for (int half = 0; half < 2; half++) {
                const long row = brow + rowBase + mi*16 + gID + half*8;
                float v0 = acc[mi][ni][half*2]   + b0;
                float v1 = acc[mi][ni][half*2+1] + b1;
                if (mode == 1) {
                    v0 = __fdividef(v0, 1.f + __expf(-v0));
                    v1 = __fdividef(v1, 1.f + __expf(-v1));
                }
                if (Ch) *(__half2*)&Ch[row * N + col] = __floats2half2_rn(v0, v1);
                else    *(float2*)&Cf[row * N + col] = make_float2(v0, v1);
            }
        }
    }
}

// ---------------------------------------------------------------------------
// fp16 GEMM + fused residual/LayerNorm. tile 128x256, 512 thr, BK=64,
// 2-stage pipeline (3 stages would drop to 1 CTA/SM).
// ---------------------------------------------------------------------------
#define TILE_A2 (128*PROW)           // 18432
#define TILE_B2 (256*PROW)           // 36864
#define OFF_B2  TILE_A2
#define STAGE2  (TILE_A2 + TILE_B2)  // 55296
#define LN_SMEM (2*STAGE2 + 2*128*4) // 111616

__global__ __launch_bounds__(512)
void mma_gemm_ln(const __half* __restrict__ A, const __half* __restrict__ Bt,
                 int K,
                 const float* __restrict__ bias,
                 const float* __restrict__ R,
                 const float* __restrict__ gamma, const float* __restrict__ beta,
                 float* __restrict__ Cf, __half* __restrict__ Ch)
{
    extern __shared__ __align__(128) char smem[];
    const uint32_t sb = smem_u32(smem);
    float* srow  = (float*)(smem + 2*STAGE2);
    float* srow2 = srow + 128;
    const int tid = threadIdx.x;
    const int wid = tid >> 5, lane = tid & 31;
    const long brow = (long)blockIdx.y * 128;

    const int rowBase = (wid >> 3) * 64;
    const int colBase = (wid & 7) * 32;

    float acc[4][4][4];
#pragma unroll
    for (int a = 0; a < 4; a++)
#pragma unroll
        for (int b = 0; b < 4; b++)
#pragma unroll
            for (int c = 0; c < 4; c++) acc[a][b][c] = 0.f;

    const int nch = K / BK;

    auto load_stage = [&](int s, int cidx){
        const uint32_t base = sb + s * STAGE2;
        const long kc = (long)cidx * BK;
#pragma unroll
        for (int i = tid; i < 3072; i += 512) {
            const int row = i >> 3, ch = i & 7;
            if (row < 128) {
                cp_async16(base + row * PROW + ch * 16,
                           A + (brow + row) * (long)K + kc + ch * 8);
            } else {
                const int br = row - 128;
                cp_async16(base + OFF_B2 + br * PROW + ch * 16,
                           Bt + br * (long)K + kc + ch * 8);
            }
        }
        cp_commit();
    };

    load_stage(0, 0);

    const int g = lane >> 3, r = lane & 7;

    for (int c = 0; c < nch; c++) {
        if (c + 1 < nch) { load_stage((c + 1) & 1, c + 1);
                           asm volatile("cp.async.wait_group 1;" ::: "memory"); }
        else             { asm volatile("cp.async.wait_group 0;" ::: "memory"); }
        __syncthreads();

        const uint32_t st = sb + (c & 1) * STAGE2;
#pragma unroll
        for (int ks = 0; ks < 4; ks++) {
            const int k0 = ks * 16;
            uint32_t bf[2][4];
#pragma unroll
            for (int p = 0; p < 2; p++) {
                const uint32_t boff =
                    (uint32_t)(colBase + p*16 + ((g >> 1) << 3) + r) * PROW
                    + (uint32_t)(k0 + ((g & 1) << 3)) * 2;
                LDSM4(bf[p], st + OFF_B2 + boff);
            }
#pragma unroll
            for (int mi = 0; mi < 4; mi++) {
                const uint32_t aoff =
                    (uint32_t)(rowBase + mi*16 + r + ((g & 1) << 3)) * PROW
                    + (uint32_t)(k0 + ((g >> 1) << 3)) * 2;
                uint32_t af[4];
                LDSM4(af, st + aoff);
#pragma unroll
                for (int ni = 0; ni < 4; ni++) {
                    const int p = ni >> 1, q = (ni & 1) * 2;
                    MMA_F16(acc[mi][ni], af, bf[p][q], bf[p][q+1]);
                }
            }
        }
        __syncthreads();
    }

    if (tid < 128) { srow[tid] = 0.f; srow2[tid] = 0.f; }
    __syncthreads();

    const int gID = lane >> 2, tig = lane & 3;

#pragma unroll
    for (int mi = 0; mi < 4; mi++) {
#pragma unroll
        for (int half = 0; half < 2; half++) {
            const int  rloc = rowBase + mi*16 + gID + half*8;
            const long row  = brow + rloc;
            float s = 0.f, s2 = 0.f;
#pragma unroll
            for (int ni = 0; ni < 4; ni++) {
                const int col = colBase + ni*8 + tig*2;
                float2 rv = *(const float2*)&R[row * DMODEL + col];
                float v0 = acc[mi][ni][half*2]   + rv.x;
                float v1 = acc[mi][ni][half*2+1] + rv.y;
                if (bias) { v0 += __ldg(&bias[col]); v1 += __ldg(&bias[col+1]); }
                acc[mi][ni][half*2]   = v0;
                acc[mi][ni][half*2+1] = v1;
                s  += v0 + v1;
                s2 += v0*v0 + v1*v1;
            }
            atomicAdd(&srow[rloc],  s);
            atomicAdd(&srow2[rloc], s2);
        }
    }
    __syncthreads();

#pragma unroll
    for (int mi = 0; mi < 4; mi++) {
#pragma unroll
        for (int half = 0; half < 2; half++) {
            const int  rloc = rowBase + mi*16 + gID + half*8;
            const long row  = brow + rloc;
            const float mean = srow[rloc] * (1.f / DMODEL);
            float var = srow2[rloc] * (1.f / DMODEL) - mean * mean;
            const float rs = rsqrtf(var + 1e-12f);
#pragma unroll
            for (int ni = 0; ni < 4; ni++) {
                const int col = colBase + ni*8 + tig*2;
                float2 gv = *(const float2*)&gamma[col];
                float2 bv = *(const float2*)&beta[col];
                float v0 = (acc[mi][ni][half*2]   - mean) * rs * gv.x + bv.x;
                float v1 = (acc[mi][ni][half*2+1] - mean) * rs * gv.y + bv.y;
                *(float2*)&Cf[row * DMODEL + col] = make_float2(v0, v1);
                if (Ch) *(__half2*)&Ch[row * DMODEL + col] = __floats2half2_rn(v0, v1);
            }
        }
    }
}

// ---------------------------------------------------------------------------
// Prep: splam/bias + all weight transposes + x->fp16 in ONE launch
// ---------------------------------------------------------------------------
#define WT_B0 1
#define WT_B1 (WT_B0 + (DMODEL*HID2)/256)
#define WT_B2 (WT_B1 + (HID*HID2)/256)
#define WT_B3 (WT_B2 + (HID*DMODEL)/256)
#define WT_B4 (WT_B3 + (DMODEL*INNER)/256)
#define WT_B5 (WT_B4 + (INNER*DMODEL)/256)
#define XH_BLKS ((NTOK*DMODEL/4)/256)
#define WT_B6 (WT_B5 + XH_BLKS)

__global__ __launch_bounds__(256)
void prep_kernel(const float* __restrict__ Lambda, const float* __restrict__ b_gates,
                 const float* __restrict__ w_in, const float* __restrict__ w_gates,
                 const float* __restrict__ w_out, const float* __restrict__ ffn_w1,
                 const float* __restrict__ ffn_w2, const float* __restrict__ x)
{
    const int blk = blockIdx.x;
    const int t = threadIdx.x;
    if (blk == 0) {
#pragma unroll
        for (int q = 0; q < 2; q++) {
            int h = t + q * 256;
            g_splam[h] = log1pf(expf(Lambda[h]));
            g_bil[2*h]     = b_gates[h];
            g_bil[2*h + 1] = b_gates[HID + h];
        }
        return;
    }
    if (blk >= WT_B5) {
        const long i = (long)(blk - WT_B5) * 256 + t;
        float4 v = ((const float4*)x)[i];
        ((__half2*)g_xr)[2*i]   = __floats2half2_rn(v.x, v.y);
        ((__half2*)g_xr)[2*i+1] = __floats2half2_rn(v.z, v.w);
        return;
    }
    const float* W; __half* WT; int K, N, il = 0; long base;
    if (blk < WT_B1)      { W = w_in;    WT = g_wiT; K = DMODEL; N = HID2;   base = (long)(blk - WT_B0) * 256; }
    else if (blk < WT_B2) { W = w_gates; WT = g_wgT; K = HID;    N = HID2;   base = (long)(blk - WT_B1) * 256; il = 1; }
    else if (blk < WT_B3) { W = w_out;   WT = g_woT; K = HID;    N = DMODEL; base = (long)(blk - WT_B2) * 256; }
    else if (blk < WT_B4) { W = ffn_w1;  WT = g_f1T; K = DMODEL; N = INNER;  base = (long)(blk - WT_B3) * 256; }
    else                  { W = ffn_w2;  WT = g_f2T; K = INNER;  N = DMODEL; base = (long)(blk - WT_B4) * 256; }
    const long i = base + t;
    const int k = (int)(i % K);
    const int n = (int)(i / K);
    const int col = il ? ((n >> 1) + (n & 1) * HID) : n;
    WT[i] = __float2half_rn(W[(long)k * N + col]);
}

// ---------------------------------------------------------------------------
// Sliding-window causal depthwise conv (K=4) + bias + silu. b0 = batch offset
// ---------------------------------------------------------------------------
__global__ __launch_bounds__(256)
void conv_silu_kernel(const float* __restrict__ conv_w,
                      const float* __restrict__ conv_b, int b0)
{
    const int h2 = threadIdx.x;
    const int b  = b0 + blockIdx.y;
    const int t0 = blockIdx.x * CONV_CHUNK;
    const int h  = h2 << 1;

    const float4 wa = *(const float4*)&conv_w[h * 4];
    const float4 wb = *(const float4*)&conv_w[h * 4 + 4];
    const float  ca = conv_b[h], cb = conv_b[h + 1];

    const __half2* xz = (const __half2*)g_xzh;
    const long rs = HID2 / 2;
    long base = ((long)b * SEQ + t0) * rs + h2;

    float a0 = 0.f, a1 = 0.f, a2 = 0.f;
    float b0f = 0.f, b1f = 0.f, b2f = 0.f;
    if (t0 >= 3) {
        __half2 p;
        p = xz[base - 3*rs]; a0 = __low2float(p); b0f = __high2float(p);
        p = xz[base - 2*rs]; a1 = __low2float(p); b1f = __high2float(p);
        p = xz[base - 1*rs]; a2 = __low2float(p); b2f = __high2float(p);
    }

    __half2* xcp = (__half2*)g_xc;
    long ob = ((long)b * SEQ + t0) * (HID / 2) + h2;

#pragma unroll 4
    for (int t = 0; t < CONV_CHUNK; t++) {
        const __half2 cur = xz[base]; base += rs;
        const float xa = __low2float(cur), xb = __high2float(cur);
        float va = ca, vb = cb;
        va = fmaf(wa.x, a0, va); va = fmaf(wa.y, a1, va);
        va = fmaf(wa.z, a2, va); va = fmaf(wa.w, xa, va);
        vb = fmaf(wb.x, b0f, vb); vb = fmaf(wb.y, b1f, vb);
        vb = fmaf(wb.z, b2f, vb); vb = fmaf(wb.w, xb, vb);
        a0 = a1; a1 = a2; a2 = xa;
        b0f = b1f; b1f = b2f; b2f = xb;
        va = __fdividef(va, 1.f + __expf(-va));
        vb = __fdividef(vb, 1.f + __expf(-vb));
        xcp[ob] = __floats2half2_rn(va, vb);
        ob += HID / 2;
    }
}

// ---------------------------------------------------------------------------
// scanC: 2 channels per thread; carry recomputed in-block. b0 = batch offset
// ---------------------------------------------------------------------------
__global__ __launch_bounds__(256)
void scanC_kernel(int b0)
{
    const int tid = threadIdx.x;
    const int c = blockIdx.x % NC;
    const int b = b0 + blockIdx.x / NC;
    const int h = tid << 1;

    float hx = 0.f, hy = 0.f;
    for (int j = 0; j < c; j++) {
        const int i = (b*NC + j)*HID + h;
        const float2 a  = *(const float2*)&g_cA[i];
        const float2 bb = *(const float2*)&g_cB[i];
        hx = fmaf(a.x, hx, bb.x);
        hy = fmaf(a.y, hy, bb.y);
    }

    long base  = ((long)b*SEQ + c*CLEN)*HID  + h;
    long zbase = ((long)b*SEQ + c*CLEN)*HID2 + HID + h;
    for (int t = 0; t < CLEN; t++) {
        const uint2 pk2 = *(const uint2*)&g_ab[base];
        const __half2 p0 = *(const __half2*)&pk2.x;
        const __half2 p1 = *(const __half2*)&pk2.y;
        const float om0 = __low2float(p0), bp0 = __high2float(p0);
        const float om1 = __low2float(p1), bp1 = __high2float(p1);
        hx = fmaf(-om0, hx, hx) + bp0;
        hy = fmaf(-om1, hy, hy) + bp1;
        const __half2 zz = *(const __half2*)&g_xzh[zbase];
        const float z0 = __low2float(zz), z1 = __high2float(zz);
        const float s0 = __fdividef(z0, 1.f + __expf(-z0));
        const float s1 = __fdividef(z1, 1.f + __expf(-z1));
        *(__half2*)&g_y[base] = __floats2half2_rn(s0 * hx, s1 * hy);
        base  += HID;
        zbase += HID2;
    }
}

// ---------------------------------------------------------------------------
// Launch: two fully independent half-batch pipelines on two streams
// ---------------------------------------------------------------------------
extern "C" void kernel_launch(void* const* d_in, const int* in_sizes, int n_in,
                              void* d_out, int out_size)
{
    const float* x      = (const float*)d_in[0];
    const float* w_in   = (const float*)d_in[1];
    const float* conv_w = (const float*)d_in[2];
    const float* conv_b = (const float*)d_in[3];
    const float* w_gates= (const float*)d_in[4];
    const float* b_gates= (const float*)d_in[5];
    const float* Lambda = (const float*)d_in[6];
    const float* w_out  = (const float*)d_in[7];
    const float* ln1_g  = (const float*)d_in[8];
    const float* ln1_b  = (const float*)d_in[9];
    const float* ffn_w1 = (const float*)d_in[10];
    const float* ffn_b1 = (const float*)d_in[11];
    const float* ffn_w2 = (const float*)d_in[12];
    const float* ffn_b2 = (const float*)d_in[13];
    const float* ln2_g  = (const float*)d_in[14];
    const float* ln2_b  = (const float*)d_in[15];
    float* dout = (float*)d_out;

    static cudaStream_t s2 = nullptr;
    static cudaEvent_t evFork = nullptr, evB = nullptr;
    static bool init_done = false;
    if (!init_done) {
        cudaFuncSetAttribute(mma_gemm,    cudaFuncAttributeMaxDynamicSharedMemorySize, GEMM_SMEM);
        cudaFuncSetAttribute(mma_gemm_ln, cudaFuncAttributeMaxDynamicSharedMemorySize, LN_SMEM);
        cudaStreamCreateWithFlags(&s2, cudaStreamNonBlocking);
        cudaEventCreateWithFlags(&evFork, cudaEventDisableTiming);
        cudaEventCreateWithFlags(&evB,    cudaEventDisableTiming);
        init_done = true;
    }

    float *hs;
    __half *xzh, *xr, *xc, *y, *hsh, *ff1, *wiT, *wgT, *woT, *f1T, *f2T;
    cudaGetSymbolAddress((void**)&hs,  g_hs);
    cudaGetSymbolAddress((void**)&xzh, g_xzh);
    cudaGetSymbolAddress((void**)&xr,  g_xr);
    cudaGetSymbolAddress((void**)&xc,  g_xc);
    cudaGetSymbolAddress((void**)&y,   g_y);
    cudaGetSymbolAddress((void**)&hsh, g_hsh);
    cudaGetSymbolAddress((void**)&ff1, g_ff1);
    cudaGetSymbolAddress((void**)&wiT, g_wiT);
    cudaGetSymbolAddress((void**)&wgT, g_wgT);
    cudaGetSymbolAddress((void**)&woT, g_woT);
    cudaGetSymbolAddress((void**)&f1T, g_f1T);
    cudaGetSymbolAddress((void**)&f2T, g_f2T);

    const size_t oD = (size_t)HROWS * DMODEL;
    const size_t oH = (size_t)HROWS * HID;
    const size_t oZ = (size_t)HROWS * HID2;
    const size_t oI = (size_t)HROWS * INNER;

    prep_kernel<<<WT_B6, 256>>>(Lambda, b_gates, w_in, w_gates, w_out,
                                ffn_w1, ffn_w2, x);
    cudaEventRecord(evFork, 0);
    cudaStreamWaitEvent(s2, evFork, 0);

    // ================= half A (batches 0..15) on main stream =================
    mma_gemm<<<dim3(4, HROWS/128), 256, GEMM_SMEM>>>(            // xh_A
        xr, wiT, HROWS, HID2, DMODEL, 0, 0, nullptr, 0, nullptr, xzh);
    conv_silu_kernel<<<dim3(SEQ/CONV_CHUNK, HBATCH), 256>>>(conv_w, conv_b, 0);
    mma_gemm<<<dim3(HID2/128, HROWS/128), 256, GEMM_SMEM>>>(     // gates_A
        xc, wgT, HROWS, HID2, HID, 0, 0, nullptr, 2, nullptr, nullptr);
    mma_gemm<<<dim3(4, HROWS/128), 256, GEMM_SMEM>>>(            // z_A
        xr, wiT, HROWS, HID2, DMODEL, 512, 0, nullptr, 0, nullptr, xzh);
    scanC_kernel<<<HBATCH*NC, 256>>>(0);
    mma_gemm_ln<<<dim3(1, HROWS/128), 512, LN_SMEM>>>(           // LN1_A
        y, woT, HID, nullptr, x, ln1_g, ln1_b, hs, hsh);
    mma_gemm<<<dim3(INNER/128, HROWS/128), 256, GEMM_SMEM>>>(    // ffn1_A
        hsh, f1T, HROWS, INNER, DMODEL, 0, 0, ffn_b1, 1, nullptr, ff1);
    mma_gemm_ln<<<dim3(1, HROWS/128), 512, LN_SMEM>>>(           // ffn2_A
        ff1, f2T, INNER, ffn_b2, hs, ln2_g, ln2_b, dout, nullptr);

    // ================= half B (batches 16..31) on side stream ================
    mma_gemm<<<dim3(4, HROWS/128), 256, GEMM_SMEM, s2>>>(        // z_B
        xr + oD, wiT, HROWS, HID2, DMODEL, 512, 0, nullptr, 0, nullptr, xzh + oZ);
    mma_gemm<<<dim3(4, HROWS/128), 256, GEMM_SMEM, s2>>>(        // xh_B
        xr + oD, wiT, HROWS, HID2, DMODEL, 0, 0, nullptr, 0, nullptr, xzh + oZ);
    conv_silu_kernel<<<dim3(SEQ/CONV_CHUNK, HBATCH), 256, 0, s2>>>(conv_w, conv_b, HBATCH);
    mma_gemm<<<dim3(HID2/128, HROWS/128), 256, GEMM_SMEM, s2>>>( // gates_B
        xc + oH, wgT, HROWS, HID2, HID, 0, HROWS, nullptr, 2, nullptr, nullptr);
    scanC_kernel<<<HBATCH*NC, 256, 0, s2>>>(HBATCH);
    mma_gemm_ln<<<dim3(1, HROWS/128), 512, LN_SMEM, s2>>>(       // LN1_B
        y + oH, woT, HID, nullptr, x + oD, ln1_g, ln1_b, hs + oD, hsh + oD);
    mma_gemm<<<dim3(INNER/128, HROWS/128), 256, GEMM_SMEM, s2>>>(// ffn1_B
        hsh + oD, f1T, HROWS, INNER, DMODEL, 0, 0, ffn_b1, 1, nullptr, ff1 + oI);
    mma_gemm_ln<<<dim3(1, HROWS/128), 512, LN_SMEM, s2>>>(       // ffn2_B
        ff1 + oI, f2T, INNER, ffn_b2, hs + oD, ln2_g, ln2_b, dout + oD, nullptr);
    cudaEventRecord(evB, s2);

    cudaStreamWaitEvent(0, evB, 0);
}

// round 17
// speedup vs baseline: 1.0186x; 1.0186x over previous
#include <cuda_runtime.h>
#include <cuda_fp16.h>
#include <math.h>
#include <stdint.h>

#define BATCH  32
#define SEQ    2048
#define DMODEL 256
#define HID    512
#define HID2   1024
#define INNER  1024
#define NTOK   (BATCH*SEQ)   // 65536
#define NC     32
#define CLEN   (SEQ/NC)      // 64
#define CONV_CHUNK 32
#define HBATCH (BATCH/2)
#define HROWS  (NTOK/2)      // 32768

// ---------------------------------------------------------------------------
// Scratch
// ---------------------------------------------------------------------------
__device__ float g_hs   [(size_t)NTOK*DMODEL];
__device__ float g_cA   [BATCH*NC*HID];
__device__ float g_cB   [BATCH*NC*HID];
__device__ float g_splam[HID];
__device__ float g_bil  [HID2];
__device__ __align__(256) __half2 g_ab[(size_t)NTOK*HID];
__device__ __align__(256) __half g_xzh[(size_t)NTOK*HID2];  // [xh | z]
__device__ __align__(256) __half g_xr [(size_t)NTOK*DMODEL];
__device__ __align__(256) __half g_xc [(size_t)NTOK*HID];
__device__ __align__(256) __half g_y  [(size_t)NTOK*HID];
__device__ __align__(256) __half g_hsh[(size_t)NTOK*DMODEL];
__device__ __align__(256) __half g_ff1[(size_t)NTOK*INNER];
__device__ __align__(256) __half g_wiT[HID2*DMODEL];
__device__ __align__(256) __half g_wgT[HID2*HID];
__device__ __align__(256) __half g_woT[DMODEL*HID];
__device__ __align__(256) __half g_f1T[INNER*DMODEL];
__device__ __align__(256) __half g_f2T[DMODEL*INNER];

// ---------------------------------------------------------------------------
// helpers
// ---------------------------------------------------------------------------
__device__ __forceinline__ uint32_t smem_u32(const void* p){
    uint32_t a;
    asm("{ .reg .u64 t; cvta.to.shared.u64 t, %1; cvt.u32.u64 %0, t; }"
        : "=r"(a) : "l"(p));
    return a;
}
__device__ __forceinline__ void cp_async16(uint32_t dst, const void* src){
    asm volatile("cp.async.cg.shared.global [%0], [%1], 16;" :: "r"(dst), "l"(src));
}
__device__ __forceinline__ void cp_commit(){ asm volatile("cp.async.commit_group;"); }

#define LDSM4(R, A) \
    asm volatile("ldmatrix.sync.aligned.m8n8.x4.shared.b16 {%0,%1,%2,%3}, [%4];" \
        : "=r"((R)[0]),"=r"((R)[1]),"=r"((R)[2]),"=r"((R)[3]) : "r"(A))

#define MMA_F16(C, A, B0, B1) \
    asm volatile("mma.sync.aligned.m16n8k16.row.col.f32.f16.f16.f32 " \
        "{%0,%1,%2,%3},{%4,%5,%6,%7},{%8,%9},{%0,%1,%2,%3};" \
        : "+f"((C)[0]),"+f"((C)[1]),"+f"((C)[2]),"+f"((C)[3]) \
        : "r"((A)[0]),"r"((A)[1]),"r"((A)[2]),"r"((A)[3]),"r"(B0),"r"(B1))

// ---------------------------------------------------------------------------
// fp16 GEMM (128x128 tile, 256 thr, BK=64, PROW=144), 2-stage pipeline (R14)
// mode: 0 = plain, 1 = silu, 2 = fused gates epilogue (+2 chunk scanA's)
// ---------------------------------------------------------------------------
#define BK    64
#define PROW  144                  // 128 data bytes + 16 pad
#define SZ_T  (128*PROW)           // 18432
#define OFF_B SZ_T
#define STAGE (2*SZ_T)             // 36864
#define GEMM_SMEM (2*STAGE)        // 73728 >= mode-2 overlay 34816

__global__ __launch_bounds__(256)
void mma_gemm(const __half* __restrict__ A, const __half* __restrict__ Bt,
              int M, int N, int K, int col0, int row0,
              const float* __restrict__ bias, int mode,
              float* __restrict__ Cf, __half* __restrict__ Ch)
{
    extern __shared__ __align__(128) char smem[];
    const uint32_t sb = smem_u32(smem);
    const int tid = threadIdx.x;
    const int wid = tid >> 5, lane = tid & 31;
    const long brow = (long)blockIdx.y * 128;
    const long bcol = (long)col0 + (long)blockIdx.x * 128;

    const int rowBase = (wid >> 2) * 64;
    const int colBase = (wid & 3) * 32;

    float acc[4][4][4];
#pragma unroll
    for (int a = 0; a < 4; a++)
#pragma unroll
        for (int b = 0; b < 4; b++)
#pragma unroll
            for (int c = 0; c < 4; c++) acc[a][b][c] = 0.f;

    const int nch = K / BK;

    auto load_stage = [&](int s, int cidx){
        const uint32_t base = sb + s * STAGE;
        const long kc = (long)cidx * BK;
#pragma unroll
        for (int i = tid; i < 1024; i += 256) {
            const int row = i >> 3, ch = i & 7;
            const uint32_t d = row * PROW + ch * 16;
            cp_async16(base + d,         A  + (brow + row) * (long)K + kc + ch * 8);
            cp_async16(base + OFF_B + d, Bt + (bcol + row) * (long)K + kc + ch * 8);
        }
        cp_commit();
    };

    load_stage(0, 0);

    const int g = lane >> 3, r = lane & 7;

    for (int c = 0; c < nch; c++) {
        if (c + 1 < nch) { load_stage((c + 1) & 1, c + 1);
                           asm volatile("cp.async.wait_group 1;" ::: "memory"); }
        else             { asm volatile("cp.async.wait_group 0;" ::: "memory"); }
        __syncthreads();

        const uint32_t st = sb + (c & 1) * STAGE;
#pragma unroll
        for (int ks = 0; ks < 4; ks++) {
            const int k0 = ks * 16;
            uint32_t bf[2][4];
#pragma unroll
            for (int p = 0; p < 2; p++) {
                const uint32_t boff =
                    (uint32_t)(colBase + p*16 + ((g >> 1) << 3) + r) * PROW
                    + (uint32_t)(k0 + ((g & 1) << 3)) * 2;
                LDSM4(bf[p], st + OFF_B + boff);
            }
#pragma unroll
            for (int mi = 0; mi < 4; mi++) {
                const uint32_t aoff =
                    (uint32_t)(rowBase + mi*16 + r + ((g & 1) << 3)) * PROW
                    + (uint32_t)(k0 + ((g >> 1) << 3)) * 2;
                uint32_t af[4];
                LDSM4(af, st + aoff);
#pragma unroll
                for (int ni = 0; ni < 4; ni++) {
                    const int p = ni >> 1, q = (ni & 1) * 2;
                    MMA_F16(acc[mi][ni], af, bf[p][q], bf[p][q+1]);
                }
            }
        }
        __syncthreads();
    }

    const int gID = lane >> 2, tig = lane & 3;

    if (mode == 2) {
        // fused gates epilogue; tile rows = 2 scan chunks of CLEN=64
        __half2* sAB  = (__half2*)smem;
        float*   segb = (float*)(smem + 128*64*4);
#pragma unroll
        for (int mi = 0; mi < 4; mi++) {
#pragma unroll
            for (int ni = 0; ni < 4; ni++) {
                const long col = bcol + colBase + ni*8 + tig*2;
                const int hloc = (colBase >> 1) + ni*4 + tig;
                const int h    = (int)(col >> 1);
#pragma unroll
                for (int half = 0; half < 2; half++) {
                    const int  rloc = rowBase + mi*16 + gID + half*8;
                    const long arow = (long)row0 + brow + rloc;
                    const float rec = acc[mi][ni][half*2]   + g_bil[col];
                    const float inp = acc[mi][ni][half*2+1] + g_bil[col + 1];
                    const float sp = g_splam[h];
                    const float sr = __fdividef(1.f, 1.f + __expf(-rec));
                    const float om = -expm1f(-sp * sr);          // 1 - alpha
                    const float a  = 1.f - om;
                    const float si = __fdividef(1.f, 1.f + __expf(-inp));
                    const float xc = __half2float(g_xc[arow * HID + h]);
                    const float bp = sqrtf(1.f - a*a + 1e-8f) * si * xc;
                    const __half2 pk = __floats2half2_rn(om, bp);
                    g_ab[arow * HID + h] = pk;
                    sAB[rloc * 64 + hloc] = pk;
                }
            }
        }
        __syncthreads();
        const int ch  = tid & 63;
        const int seg = tid >> 6;
        const long abrow = (long)row0 + brow;
        const int b   = (int)(abrow >> 11);
        const int cc0 = (int)((abrow >> 6) & (NC - 1));
#pragma unroll
        for (int sub = 0; sub < 2; sub++) {
            float Aprod = 1.f, Bacc = 0.f;
            int rr = sub * 64 + seg * 16;
#pragma unroll 8
            for (int t = 0; t < 16; t++, rr++) {
                const __half2 pk = sAB[rr * 64 + ch];
                const float a = 1.f - __low2float(pk);
                const float p = __high2float(pk);
                Bacc = fmaf(a, Bacc, p);
                Aprod *= a;
            }
            segb[(ch * 4 + seg) * 2]     = Aprod;
            segb[(ch * 4 + seg) * 2 + 1] = Bacc;
            __syncthreads();
            if (tid < 64) {
                float At = 1.f, Bv = 0.f;
#pragma unroll
                for (int s2 = 0; s2 < 4; s2++) {
                    const float a = segb[(tid * 4 + s2) * 2];
                    const float p = segb[(tid * 4 + s2) * 2 + 1];
                    Bv = fmaf(a, Bv, p);
                    At *= a;
                }
                const int h = (int)(bcol >> 1) + tid;
                g_cA[(b*NC + cc0 + sub)*HID + h] = At;
                g_cB[(b*NC + cc0 + sub)*HID + h] = Bv;
            }
            __syncthreads();
        }
        return;
    }

#pragma unroll
    for (int mi = 0; mi < 4; mi++) {
#pragma unroll
        for (int ni = 0; ni < 4; ni++) {
            const long col = bcol + colBase + ni*8 + tig*2;
            float b0 = 0.f, b1 = 0.f;
            if (bias) { b0 = __ldg(&bias[col]); b1 = __ldg(&bias[col+1]); }
#pragma unroll
            for (int half = 0; half < 2; half++) {
                const long row = brow + rowBase + mi*16 + gID + half*8;
                float v0 = acc[mi][ni][half*2]   + b0;
                float v1 = acc[mi][ni][half*2+1] + b1;
                if (mode == 1) {
                    v0 = __fdividef(v0, 1.f + __expf(-v0));
                    v1 = __fdividef(v1, 1.f + __expf(-v1));
                }
                if (Ch) *(__half2*)&Ch[row * N + col] = __floats2half2_rn(v0, v1);
                else    *(float2*)&Cf[row * N + col] = make_float2(v0, v1);
            }
        }
    }
}

// ---------------------------------------------------------------------------
// fp16 GEMM + fused residual/LayerNorm. tile 128x256, 512 thr, BK=64 (R14)
// ---------------------------------------------------------------------------
#define TILE_A2 (128*PROW)           // 18432
#define TILE_B2 (256*PROW)           // 36864
#define OFF_B2  TILE_A2
#define STAGE2  (TILE_A2 + TILE_B2)  // 55296
#define LN_SMEM (2*STAGE2 + 2*128*4) // 111616

__global__ __launch_bounds__(512)
void mma_gemm_ln(const __half* __restrict__ A, const __half* __restrict__ Bt,
                 int K,
                 const float* __restrict__ bias,
                 const float* __restrict__ R,
                 const float* __restrict__ gamma, const float* __restrict__ beta,
                 float* __restrict__ Cf, __half* __restrict__ Ch)
{
    extern __shared__ __align__(128) char smem[];
    const uint32_t sb = smem_u32(smem);
    float* srow  = (float*)(smem + 2*STAGE2);
    float* srow2 = srow + 128;
    const int tid = threadIdx.x;
    const int wid = tid >> 5, lane = tid & 31;
    const long brow = (long)blockIdx.y * 128;

    const int rowBase = (wid >> 3) * 64;
    const int colBase = (wid & 7) * 32;

    float acc[4][4][4];
#pragma unroll
    for (int a = 0; a < 4; a++)
#pragma unroll
        for (int b = 0; b < 4; b++)
#pragma unroll
            for (int c = 0; c < 4; c++) acc[a][b][c] = 0.f;

    const int nch = K / BK;

    auto load_stage = [&](int s, int cidx){
        const uint32_t base = sb + s * STAGE2;
        const long kc = (long)cidx * BK;
#pragma unroll
        for (int i = tid; i < 3072; i += 512) {
            const int row = i >> 3, ch = i & 7;
            if (row < 128) {
                cp_async16(base + row * PROW + ch * 16,
                           A + (brow + row) * (long)K + kc + ch * 8);
            } else {
                const int br = row - 128;
                cp_async16(base + OFF_B2 + br * PROW + ch * 16,
                           Bt + br * (long)K + kc + ch * 8);
            }
        }
        cp_commit();
    };

    load_stage(0, 0);

    const int g = lane >> 3, r = lane & 7;

    for (int c = 0; c < nch; c++) {
        if (c + 1 < nch) { load_stage((c + 1) & 1, c + 1);
                           asm volatile("cp.async.wait_group 1;" ::: "memory"); }
        else             { asm volatile("cp.async.wait_group 0;" ::: "memory"); }
        __syncthreads();

        const uint32_t st = sb + (c & 1) * STAGE2;
#pragma unroll
        for (int ks = 0; ks < 4; ks++) {
            const int k0 = ks * 16;
            uint32_t bf[2][4];
#pragma unroll
            for (int p = 0; p < 2; p++) {
                const uint32_t boff =
                    (uint32_t)(colBase + p*16 + ((g >> 1) << 3) + r) * PROW
                    + (uint32_t)(k0 + ((g & 1) << 3)) * 2;
                LDSM4(bf[p], st + OFF_B2 + boff);
            }
#pragma unroll
            for (int mi = 0; mi < 4; mi++) {
                const uint32_t aoff =
                    (uint32_t)(rowBase + mi*16 + r + ((g & 1) << 3)) * PROW
                    + (uint32_t)(k0 + ((g >> 1) << 3)) * 2;
                uint32_t af[4];
                LDSM4(af, st + aoff);
#pragma unroll
                for (int ni = 0; ni < 4; ni++) {
                    const int p = ni >> 1, q = (ni & 1) * 2;
                    MMA_F16(acc[mi][ni], af, bf[p][q], bf[p][q+1]);
                }
            }
        }
        __syncthreads();
    }

    if (tid < 128) { srow[tid] = 0.f; srow2[tid] = 0.f; }
    __syncthreads();

    const int gID = lane >> 2, tig = lane & 3;

#pragma unroll
    for (int mi = 0; mi < 4; mi++) {
#pragma unroll
        for (int half = 0; half < 2; half++) {
            const int  rloc = rowBase + mi*16 + gID + half*8;
            const long row  = brow + rloc;
            float s = 0.f, s2 = 0.f;
#pragma unroll
            for (int ni = 0; ni < 4; ni++) {
                const int col = colBase + ni*8 + tig*2;
                float2 rv = *(const float2*)&R[row * DMODEL + col];
                float v0 = acc[mi][ni][half*2]   + rv.x;
                float v1 = acc[mi][ni][half*2+1] + rv.y;
                if (bias) { v0 += __ldg(&bias[col]); v1 += __ldg(&bias[col+1]); }
                acc[mi][ni][half*2]   = v0;
                acc[mi][ni][half*2+1] = v1;
                s  += v0 + v1;
                s2 += v0*v0 + v1*v1;
            }
            atomicAdd(&srow[rloc],  s);
            atomicAdd(&srow2[rloc], s2);
        }
    }
    __syncthreads();

#pragma unroll
    for (int mi = 0; mi < 4; mi++) {
#pragma unroll
        for (int half = 0; half < 2; half++) {
            const int  rloc = rowBase + mi*16 + gID + half*8;
            const long row  = brow + rloc;
            const float mean = srow[rloc] * (1.f / DMODEL);
            float var = srow2[rloc] * (1.f / DMODEL) - mean * mean;
            const float rs = rsqrtf(var + 1e-12f);
#pragma unroll
            for (int ni = 0; ni < 4; ni++) {
                const int col = colBase + ni*8 + tig*2;
                float2 gv = *(const float2*)&gamma[col];
                float2 bv = *(const float2*)&beta[col];
                float v0 = (acc[mi][ni][half*2]   - mean) * rs * gv.x + bv.x;
                float v1 = (acc[mi][ni][half*2+1] - mean) * rs * gv.y + bv.y;
                *(float2*)&Cf[row * DMODEL + col] = make_float2(v0, v1);
                if (Ch) *(__half2*)&Ch[row * DMODEL + col] = __floats2half2_rn(v0, v1);
            }
        }
    }
}

// ---------------------------------------------------------------------------
// Prep split: early (splam/bias + wiT + wgT); late (woT/f1T/f2T) on s2.
// ---------------------------------------------------------------------------
#define PE_B1 1
#define PE_B2 (PE_B1 + (DMODEL*HID2)/256)
#define PE_B3 (PE_B2 + (HID*HID2)/256)

__global__ __launch_bounds__(256)
void prep_early(const float* __restrict__ Lambda, const float* __restrict__ b_gates,
                const float* __restrict__ w_in, const float* __restrict__ w_gates)
{
    const int blk = blockIdx.x;
    const int t = threadIdx.x;
    if (blk == 0) {
#pragma unroll
        for (int q = 0; q < 2; q++) {
            int h = t + q * 256;
            g_splam[h] = log1pf(expf(Lambda[h]));
            g_bil[2*h]     = b_gates[h];
            g_bil[2*h + 1] = b_gates[HID + h];
        }
        return;
    }
    const float* W; __half* WT; int K, N, il = 0; long base;
    if (blk < PE_B2) { W = w_in;    WT = g_wiT; K = DMODEL; N = HID2; base = (long)(blk - PE_B1) * 256; }
    else             { W = w_gates; WT = g_wgT; K = HID;    N = HID2; base = (long)(blk - PE_B2) * 256; il = 1; }
    const long i = base + t;
    const int k = (int)(i % K);
    const int n = (int)(i / K);
    const int col = il ? ((n >> 1) + (n & 1) * HID) : n;
    WT[i] = __float2half_rn(W[(long)k * N + col]);
}

#define PL_B1 ((HID*DMODEL)/256)
#define PL_B2 (PL_B1 + (DMODEL*INNER)/256)
#define PL_B3 (PL_B2 + (INNER*DMODEL)/256)

__global__ __launch_bounds__(256)
void prep_late(const float* __restrict__ w_out, const float* __restrict__ ffn_w1,
               const float* __restrict__ ffn_w2)
{
    const int blk = blockIdx.x;
    const int t = threadIdx.x;
    const float* W; __half* WT; int K, N; long base;
    if (blk < PL_B1)      { W = w_out;  WT = g_woT; K = HID;    N = DMODEL; base = (long)blk * 256; }
    else if (blk < PL_B2) { W = ffn_w1; WT = g_f1T; K = DMODEL; N = INNER;  base = (long)(blk - PL_B1) * 256; }
    else                  { W = ffn_w2; WT = g_f2T; K = INNER;  N = DMODEL; base = (long)(blk - PL_B2) * 256; }
    const long i = base + t;
    const int k = (int)(i % K);
    const int n = (int)(i / K);
    WT[i] = __float2half_rn(W[(long)k * N + n]);
}

__global__ void x2h_kernel(const float* __restrict__ in, long n4,
                           __half* __restrict__ out)
{
    long i = (long)blockIdx.x * blockDim.x + threadIdx.x;
    if (i >= n4) return;
    float4 v = ((const float4*)in)[i];
    ((__half2*)out)[2*i]   = __floats2half2_rn(v.x, v.y);
    ((__half2*)out)[2*i+1] = __floats2half2_rn(v.z, v.w);
}

// ---------------------------------------------------------------------------
// Sliding-window causal depthwise conv (K=4) + bias + silu. b0 = batch offset
// ---------------------------------------------------------------------------
__global__ __launch_bounds__(256)
void conv_silu_kernel(const float* __restrict__ conv_w,
                      const float* __restrict__ conv_b, int b0)
{
    const int h2 = threadIdx.x;
    const int b  = b0 + blockIdx.y;
    const int t0 = blockIdx.x * CONV_CHUNK;
    const int h  = h2 << 1;

    const float4 wa = *(const float4*)&conv_w[h * 4];
    const float4 wb = *(const float4*)&conv_w[h * 4 + 4];
    const float  ca = conv_b[h], cb = conv_b[h + 1];

    const __half2* xz = (const __half2*)g_xzh;
    const long rs = HID2 / 2;
    long base = ((long)b * SEQ + t0) * rs + h2;

    float a0 = 0.f, a1 = 0.f, a2 = 0.f;
    float b0f = 0.f, b1f = 0.f, b2f = 0.f;
    if (t0 >= 3) {
        __half2 p;
        p = xz[base - 3*rs]; a0 = __low2float(p); b0f = __high2float(p);
        p = xz[base - 2*rs]; a1 = __low2float(p); b1f = __high2float(p);
        p = xz[base - 1*rs]; a2 = __low2float(p); b2f = __high2float(p);
    }

    __half2* xcp = (__half2*)g_xc;
    long ob = ((long)b * SEQ + t0) * (HID / 2) + h2;

#pragma unroll 4
    for (int t = 0; t < CONV_CHUNK; t++) {
        const __half2 cur = xz[base]; base += rs;
        const float xa = __low2float(cur), xb = __high2float(cur);
        float va = ca, vb = cb;
        va = fmaf(wa.x, a0, va); va = fmaf(wa.y, a1, va);
        va = fmaf(wa.z, a2, va); va = fmaf(wa.w, xa, va);
        vb = fmaf(wb.x, b0f, vb); vb = fmaf(wb.y, b1f, vb);
        vb = fmaf(wb.z, b2f, vb); vb = fmaf(wb.w, xb, vb);
        a0 = a1; a1 = a2; a2 = xa;
        b0f = b1f; b1f = b2f; b2f = xb;
        va = __fdividef(va, 1.f + __expf(-va));
        vb = __fdividef(vb, 1.f + __expf(-vb));
        xcp[ob] = __floats2half2_rn(va, vb);
        ob += HID / 2;
    }
}

// ---------------------------------------------------------------------------
// scanC: 2 channels per thread; carry recomputed in-block. b0 = batch offset
// ---------------------------------------------------------------------------
__global__ __launch_bounds__(256)
void scanC_kernel(int b0)
{
    const int tid = threadIdx.x;
    const int c = blockIdx.x % NC;
    const int b = b0 + blockIdx.x / NC;
    const int h = tid << 1;

    float hx = 0.f, hy = 0.f;
    for (int j = 0; j < c; j++) {
        const int i = (b*NC + j)*HID + h;
        const float2 a  = *(const float2*)&g_cA[i];
        const float2 bb = *(const float2*)&g_cB[i];
        hx = fmaf(a.x, hx, bb.x);
        hy = fmaf(a.y, hy, bb.y);
    }

    long base  = ((long)b*SEQ + c*CLEN)*HID  + h;
    long zbase = ((long)b*SEQ + c*CLEN)*HID2 + HID + h;
    for (int t = 0; t < CLEN; t++) {
        const uint2 pk2 = *(const uint2*)&g_ab[base];
        const __half2 p0 = *(const __half2*)&pk2.x;
        const __half2 p1 = *(const __half2*)&pk2.y;
        const float om0 = __low2float(p0), bp0 = __high2float(p0);
        const float om1 = __low2float(p1), bp1 = __high2float(p1);
        hx = fmaf(-om0, hx, hx) + bp0;
        hy = fmaf(-om1, hy, hy) + bp1;
        const __half2 zz = *(const __half2*)&g_xzh[zbase];
        const float z0 = __low2float(zz), z1 = __high2float(zz);
        const float s0 = __fdividef(z0, 1.f + __expf(-z0));
        const float s1 = __fdividef(z1, 1.f + __expf(-z1));
        *(__half2*)&g_y[base] = __floats2half2_rn(s0 * hx, s1 * hy);
        base  += HID;
        zbase += HID2;
    }
}

// ---------------------------------------------------------------------------
// Launch: two independent half-batch pipelines; prep split early/late.
// All event records precede their waits in enqueue order (capture-legal).
// ---------------------------------------------------------------------------
extern "C" void kernel_launch(void* const* d_in, const int* in_sizes, int n_in,
                              void* d_out, int out_size)
{
    const float* x      = (const float*)d_in[0];
    const float* w_in   = (const float*)d_in[1];
    const float* conv_w = (const float*)d_in[2];
    const float* conv_b = (const float*)d_in[3];
    const float* w_gates= (const float*)d_in[4];
    const float* b_gates= (const float*)d_in[5];
    const float* Lambda = (const float*)d_in[6];
    const float* w_out  = (const float*)d_in[7];
    const float* ln1_g  = (const float*)d_in[8];
    const float* ln1_b  = (const float*)d_in[9];
    const float* ffn_w1 = (const float*)d_in[10];
    const float* ffn_b1 = (const float*)d_in[11];
    const float* ffn_w2 = (const float*)d_in[12];
    const float* ffn_b2 = (const float*)d_in[13];
    const float* ln2_g  = (const float*)d_in[14];
    const float* ln2_b  = (const float*)d_in[15];
    float* dout = (float*)d_out;

    static cudaStream_t s2 = nullptr;
    static cudaEvent_t evFork = nullptr, evPrep = nullptr, evB = nullptr;
    static bool init_done = false;
    if (!init_done) {
        cudaFuncSetAttribute(mma_gemm,    cudaFuncAttributeMaxDynamicSharedMemorySize, GEMM_SMEM);
        cudaFuncSetAttribute(mma_gemm_ln, cudaFuncAttributeMaxDynamicSharedMemorySize, LN_SMEM);
        cudaStreamCreateWithFlags(&s2, cudaStreamNonBlocking);
        cudaEventCreateWithFlags(&evFork, cudaEventDisableTiming);
        cudaEventCreateWithFlags(&evPrep, cudaEventDisableTiming);
        cudaEventCreateWithFlags(&evB,    cudaEventDisableTiming);
        init_done = true;
    }

    float *hs;
    __half *xzh, *xr, *xc, *y, *hsh, *ff1, *wiT, *wgT, *woT, *f1T, *f2T;
    cudaGetSymbolAddress((void**)&hs,  g_hs);
    cudaGetSymbolAddress((void**)&xzh, g_xzh);
    cudaGetSymbolAddress((void**)&xr,  g_xr);
    cudaGetSymbolAddress((void**)&xc,  g_xc);
    cudaGetSymbolAddress((void**)&y,   g_y);
    cudaGetSymbolAddress((void**)&hsh, g_hsh);
    cudaGetSymbolAddress((void**)&ff1, g_ff1);
    cudaGetSymbolAddress((void**)&wiT, g_wiT);
    cudaGetSymbolAddress((void**)&wgT, g_wgT);
    cudaGetSymbolAddress((void**)&woT, g_woT);
    cudaGetSymbolAddress((void**)&f1T, g_f1T);
    cudaGetSymbolAddress((void**)&f2T, g_f2T);

    const size_t oD = (size_t)HROWS * DMODEL;
    const size_t oH = (size_t)HROWS * HID;
    const size_t oZ = (size_t)HROWS * HID2;
    const size_t oI = (size_t)HROWS * INNER;
    const long   h4 = (long)HROWS * DMODEL / 4;

    // early prep: splam/bias + wiT + wgT
    prep_early<<<PE_B3, 256>>>(Lambda, b_gates, w_in, w_gates);
    cudaEventRecord(evFork, 0);
    cudaStreamWaitEvent(s2, evFork, 0);

    // side stream FIRST so evPrep is recorded before main waits on it
    prep_late<<<PL_B3, 256, 0, s2>>>(w_out, ffn_w1, ffn_w2);
    cudaEventRecord(evPrep, s2);

    // ================= half A (batches 0..15) on main stream =================
    x2h_kernel<<<(int)((h4 + 255)/256), 256>>>(x, h4, xr);
    mma_gemm<<<dim3(4, HROWS/128), 256, GEMM_SMEM>>>(            // xh_A
        xr, wiT, HROWS, HID2, DMODEL, 0, 0, nullptr, 0, nullptr, xzh);
    conv_silu_kernel<<<dim3(SEQ/CONV_CHUNK, HBATCH), 256>>>(conv_w, conv_b, 0);
    mma_gemm<<<dim3(HID2/128, HROWS/128), 256, GEMM_SMEM>>>(     // gates_A
        xc, wgT, HROWS, HID2, HID, 0, 0, nullptr, 2, nullptr, nullptr);
    mma_gemm<<<dim3(4, HROWS/128), 256, GEMM_SMEM>>>(            // z_A
        xr, wiT, HROWS, HID2, DMODEL, 512, 0, nullptr, 0, nullptr, xzh);
    scanC_kernel<<<HBATCH*NC, 256>>>(0);
    cudaStreamWaitEvent(0, evPrep, 0);                           // woT/f1T/f2T ready
    mma_gemm_ln<<<dim3(1, HROWS/128), 512, LN_SMEM>>>(           // LN1_A
        y, woT, HID, nullptr, x, ln1_g, ln1_b, hs, hsh);
    mma_gemm<<<dim3(INNER/128, HROWS/128), 256, GEMM_SMEM>>>(    // ffn1_A
        hsh, f1T, HROWS, INNER, DMODEL, 0, 0, ffn_b1, 1, nullptr, ff1);
    mma_gemm_ln<<<dim3(1, HROWS/128), 512, LN_SMEM>>>(           // ffn2_A
        ff1, f2T, INNER, ffn_b2, hs, ln2_g, ln2_b, dout, nullptr);

    // ================= half B (batches 16..31) on side stream ================
    x2h_kernel<<<(int)((h4 + 255)/256), 256, 0, s2>>>(x + oD, h4, xr + oD);
    mma_gemm<<<dim3(4, HROWS/128), 256, GEMM_SMEM, s2>>>(        // z_B
        xr + oD, wiT, HROWS, HID2, DMODEL, 512, 0, nullptr, 0, nullptr, xzh + oZ);
    mma_gemm<<<dim3(4, HROWS/128), 256, GEMM_SMEM, s2>>>(        // xh_B
        xr + oD, wiT, HROWS, HID2, DMODEL, 0, 0, nullptr, 0, nullptr, xzh + oZ);
    conv_silu_kernel<<<dim3(SEQ/CONV_CHUNK, HBATCH), 256, 0, s2>>>(conv_w, conv_b, HBATCH);
    mma_gemm<<<dim3(HID2/128, HROWS/128), 256, GEMM_SMEM, s2>>>( // gates_B
        xc + oH, wgT, HROWS, HID2, HID, 0, HROWS, nullptr, 2, nullptr, nullptr);
    scanC_kernel<<<HBATCH*NC, 256, 0, s2>>>(HBATCH);
    mma_gemm_ln<<<dim3(1, HROWS/128), 512, LN_SMEM, s2>>>(       // LN1_B
        y + oH, woT, HID, nullptr, x + oD, ln1_g, ln1_b, hs + oD, hsh + oD);
    mma_gemm<<<dim3(INNER/128, HROWS/128), 256, GEMM_SMEM, s2>>>(// ffn1_B
        hsh + oD, f1T, HROWS, INNER, DMODEL, 0, 0, ffn_b1, 1, nullptr, ff1 + oI);
    mma_gemm_ln<<<dim3(1, HROWS/128), 512, LN_SMEM, s2>>>(       // ffn2_B
        ff1 + oI, f2T, INNER, ffn_b2, hs + oD, ln2_g, ln2_b, dout + oD, nullptr);
    cudaEventRecord(evB, s2);

    cudaStreamWaitEvent(0, evB, 0);
}